// round 16
// baseline (speedup 1.0000x reference)
#include <cuda_runtime.h>
#include <math.h>
#include <stdint.h>

// ---------------------------------------------------------------------------
// DeepseekV4LearnedRouter — 1-pass TF32 mma.sync GEMM (validated 253us config)
// + FUSED top-8 routing + in-warp bit-exact refinement.
//   Refine chain = ascending-k single-accumulator fmaf (empirically matches
//   the reference's fp32 rounding side on boundary tokens; DO NOT ALTER).
// ---------------------------------------------------------------------------

#define BM 128
#define BN 128
#define KC 32
#define SA 36                         // smem row stride (f32); conflict-free frags
#define TILE_WORDS (128 * SA)         // 4608
#define STAGE_WORDS (2 * TILE_WORDS)  // 9216
#define SMEM_BYTES (2 * STAGE_WORDS * 4)   // 73728

#define MAX_N 16384
#define MAX_E 256
#define TAU 2e-3f

__device__ float g_logits[(size_t)MAX_N * MAX_E];

__device__ __forceinline__ uint32_t smem_u32(const void* p) {
    uint32_t a;
    asm("{ .reg .u64 t; cvta.to.shared.u64 t, %1; cvt.u32.u64 %0, t; }" : "=r"(a) : "l"(p));
    return a;
}
__device__ __forceinline__ uint32_t f2tf32(float x) {
    uint32_t r;
    asm("cvt.rna.tf32.f32 %0, %1;" : "=r"(r) : "f"(x));
    return r;
}
__device__ __forceinline__ void cp_async16(uint32_t saddr, const void* g) {
    asm volatile("cp.async.cg.shared.global [%0], [%1], 16;" :: "r"(saddr), "l"(g));
}
__device__ __forceinline__ void cp_commit() {
    asm volatile("cp.async.commit_group;" ::: "memory");
}
template <int N>
__device__ __forceinline__ void cp_wait() {
    asm volatile("cp.async.wait_group %0;" :: "n"(N) : "memory");
}
__device__ __forceinline__ void mma_tf32(float* d, const uint32_t* a, const uint32_t* b) {
    asm volatile(
        "mma.sync.aligned.m16n8k8.row.col.f32.tf32.tf32.f32 "
        "{%0,%1,%2,%3}, {%4,%5,%6,%7}, {%8,%9}, {%0,%1,%2,%3};"
        : "+f"(d[0]), "+f"(d[1]), "+f"(d[2]), "+f"(d[3])
        : "r"(a[0]), "r"(a[1]), "r"(a[2]), "r"(a[3]), "r"(b[0]), "r"(b[1]));
}
__device__ __forceinline__ void warp_argmax(float& bestv, int& beste) {
#pragma unroll
    for (int off = 16; off > 0; off >>= 1) {
        const float ov = __shfl_xor_sync(0xffffffffu, bestv, off);
        const int   oe = __shfl_xor_sync(0xffffffffu, beste, off);
        if (ov > bestv || (ov == bestv && oe < beste)) { bestv = ov; beste = oe; }
    }
}

// ---------------- GEMM: logits = A @ W^T (1-pass TF32, 64x64 warp tiles) ----
__global__ __launch_bounds__(128, 2)
void gemm_tf32_kernel(const float* __restrict__ A,
                      const float* __restrict__ W,
                      float* __restrict__ C,
                      int E, int K)
{
    extern __shared__ float sm[];
    const uint32_t sbase = smem_u32(sm);

    const int tid  = threadIdx.x;
    const int lane = tid & 31;
    const int w    = tid >> 5;         // 0..3
    const int wm   = w & 1;            // m offset 64*wm
    const int wn   = w >> 1;           // n offset 64*wn
    const int g    = lane >> 2;        // 0..7
    const int t    = lane & 3;         // 0..3

    const int nBase = blockIdx.x * BN;
    const int mBase = blockIdx.y * BM;
    const int KT    = K / KC;          // 128

    const float* Ag = A + (size_t)mBase * K;
    const float* Wg = W + (size_t)nBase * K;

    auto load_stage = [&](int stage, int k0) {
        const uint32_t sA = sbase + (uint32_t)stage * STAGE_WORDS * 4;
        const uint32_t sW = sA + TILE_WORDS * 4;
#pragma unroll
        for (int i = 0; i < 8; i++) {
            const int c   = tid + i * 128;
            const int row = c >> 3;
            const int c8  = c & 7;
            cp_async16(sA + (uint32_t)(row * SA + c8 * 4) * 4,
                       Ag + (size_t)row * K + k0 + c8 * 4);
        }
#pragma unroll
        for (int i = 0; i < 8; i++) {
            const int c   = tid + i * 128;
            const int row = c >> 3;
            const int c8  = c & 7;
            cp_async16(sW + (uint32_t)(row * SA + c8 * 4) * 4,
                       Wg + (size_t)row * K + k0 + c8 * 4);
        }
        cp_commit();
    };

    float acc[4][8][4];
#pragma unroll
    for (int mt = 0; mt < 4; mt++)
#pragma unroll
        for (int nt = 0; nt < 8; nt++)
#pragma unroll
            for (int i = 0; i < 4; i++)
                acc[mt][nt][i] = 0.0f;

    load_stage(0, 0);
    load_stage(1, KC);

    for (int kt = 0; kt < KT; ++kt) {
        cp_wait<1>();
        __syncthreads();

        const float* Asm = sm + (kt & 1) * STAGE_WORDS;
        const float* Wsm = Asm + TILE_WORDS;
        const float* ap = Asm + (wm * 64 + g) * SA;
        const float* bp = Wsm + (wn * 64 + g) * SA;

#pragma unroll
        for (int ks = 0; ks < KC / 8; ks++) {
            const int k0 = ks * 8 + t;

            uint32_t Bh[16];
#pragma unroll
            for (int nt = 0; nt < 8; nt++) {
                Bh[nt * 2]     = f2tf32(bp[nt * 8 * SA + k0]);
                Bh[nt * 2 + 1] = f2tf32(bp[nt * 8 * SA + k0 + 4]);
            }
            uint32_t Ah[16];
#pragma unroll
            for (int mt = 0; mt < 4; mt++) {
                Ah[mt * 4 + 0] = f2tf32(ap[mt * 16 * SA + k0]);
                Ah[mt * 4 + 1] = f2tf32(ap[mt * 16 * SA + 8 * SA + k0]);
                Ah[mt * 4 + 2] = f2tf32(ap[mt * 16 * SA + k0 + 4]);
                Ah[mt * 4 + 3] = f2tf32(ap[mt * 16 * SA + 8 * SA + k0 + 4]);
            }

#pragma unroll
            for (int mt = 0; mt < 4; mt++)
#pragma unroll
                for (int nt = 0; nt < 8; nt++)
                    mma_tf32(acc[mt][nt], &Ah[mt * 4], &Bh[nt * 2]);
        }

        __syncthreads();
        if (kt + 2 < KT) load_stage(kt & 1, (kt + 2) * KC);
        else cp_commit();
    }

#pragma unroll
    for (int mt = 0; mt < 4; mt++) {
        const int row0 = mBase + wm * 64 + mt * 16 + g;
#pragma unroll
        for (int nt = 0; nt < 8; nt++) {
            const int col = nBase + wn * 64 + nt * 8 + 2 * t;
            float2* p0 = (float2*)(C + (size_t)row0 * E + col);
            float2* p1 = (float2*)(C + (size_t)(row0 + 8) * E + col);
            *p0 = make_float2(acc[mt][nt][0], acc[mt][nt][1]);
            *p1 = make_float2(acc[mt][nt][2], acc[mt][nt][3]);
        }
    }
}

// ---------------- fused top-8 routing + in-warp refinement ------------------
// One warp per token (e = lane*8 + j mapping, vectorized I/O). Tokens whose
// 8th/9th biased-score gap < TAU get boundary candidates re-scored via the
// EXACT ascending-k single-accumulator fmaf chain (validated), then re-routed.
__global__ __launch_bounds__(256)
void router_fused_kernel(const float* __restrict__ logits,
                         const float* __restrict__ bias,
                         const float* __restrict__ A,
                         const float* __restrict__ W,
                         float* __restrict__ probs,
                         float* __restrict__ rmap,
                         int N, int K)
{
    __shared__ float exsc_s[8][32];
    __shared__ int   exid_s[8][32];
    __shared__ int   ncs_s[8];

    const int warp = (blockIdx.x * blockDim.x + threadIdx.x) >> 5;
    const int wid  = (threadIdx.x >> 5) & 7;
    const int lane = threadIdx.x & 31;
    if (warp >= N) return;

    const float* lrow = logits + (size_t)warp * 256;

    float x[8], biasv[8];
    {
        const float4 l0 = *(const float4*)(lrow + lane * 8);
        const float4 l1 = *(const float4*)(lrow + lane * 8 + 4);
        x[0]=l0.x; x[1]=l0.y; x[2]=l0.z; x[3]=l0.w;
        x[4]=l1.x; x[5]=l1.y; x[6]=l1.z; x[7]=l1.w;
        const float4 b0 = *(const float4*)(bias + lane * 8);
        const float4 b1 = *(const float4*)(bias + lane * 8 + 4);
        biasv[0]=b0.x; biasv[1]=b0.y; biasv[2]=b0.z; biasv[3]=b0.w;
        biasv[4]=b1.x; biasv[5]=b1.y; biasv[6]=b1.z; biasv[7]=b1.w;
    }

    float score[8], selsc[8];
    bool  sel[8];
#pragma unroll
    for (int j = 0; j < 8; j++) {
        const float sp = fmaxf(x[j], 0.0f) + log1pf(expf(-fabsf(x[j])));
        score[j] = sqrtf(sp);
        selsc[j] = score[j] + biasv[j];
        sel[j] = false;
    }

    float sumw = 0.0f, v8 = 0.0f, v9 = 0.0f;
#pragma unroll
    for (int it = 0; it < 9; it++) {
        float bestv = -INFINITY;
        int bestj = -1;
#pragma unroll
        for (int j = 0; j < 8; j++)
            if (selsc[j] > bestv) { bestv = selsc[j]; bestj = j; }
        int beste = (bestj >= 0) ? (lane * 8 + bestj) : 0x7fffffff;
        warp_argmax(bestv, beste);
        if (it == 7) v8 = bestv;
        if (it == 8) { v9 = bestv; break; }
        if ((beste >> 3) == lane) {
            const int j = beste & 7;
            sel[j] = true;
            selsc[j] = -INFINITY;
            sumw += score[j];
        }
    }

    float tot = sumw;
#pragma unroll
    for (int off = 16; off > 0; off >>= 1)
        tot += __shfl_xor_sync(0xffffffffu, tot, off);
    float scale = 2.5f / fmaxf(tot, 1e-12f);

    const size_t orow = (size_t)warp * 256;
    {
        float4 p0, p1, m0, m1;
        p0.x = sel[0] ? score[0]*scale : 0.0f;  m0.x = sel[0] ? 1.0f : 0.0f;
        p0.y = sel[1] ? score[1]*scale : 0.0f;  m0.y = sel[1] ? 1.0f : 0.0f;
        p0.z = sel[2] ? score[2]*scale : 0.0f;  m0.z = sel[2] ? 1.0f : 0.0f;
        p0.w = sel[3] ? score[3]*scale : 0.0f;  m0.w = sel[3] ? 1.0f : 0.0f;
        p1.x = sel[4] ? score[4]*scale : 0.0f;  m1.x = sel[4] ? 1.0f : 0.0f;
        p1.y = sel[5] ? score[5]*scale : 0.0f;  m1.y = sel[5] ? 1.0f : 0.0f;
        p1.z = sel[6] ? score[6]*scale : 0.0f;  m1.z = sel[6] ? 1.0f : 0.0f;
        p1.w = sel[7] ? score[7]*scale : 0.0f;  m1.w = sel[7] ? 1.0f : 0.0f;
        *(float4*)(probs + orow + lane * 8)     = p0;
        *(float4*)(probs + orow + lane * 8 + 4) = p1;
        *(float4*)(rmap  + orow + lane * 8)     = m0;
        *(float4*)(rmap  + orow + lane * 8 + 4) = m1;
    }

    if ((v8 - v9) >= TAU) return;   // unambiguous token: done

    // ---- refinement path (≈10% of warps) -----------------------------------
    // rebuild selection scores (selsc was clobbered)
#pragma unroll
    for (int j = 0; j < 8; j++) selsc[j] = score[j] + biasv[j];

    // gather boundary candidates: |selsc - v8| <= TAU
    if (lane == 0) ncs_s[wid] = 0;
    __syncwarp();
#pragma unroll
    for (int j = 0; j < 8; j++) {
        if (fabsf(selsc[j] - v8) <= TAU) {
            const int slot = atomicAdd(&ncs_s[wid], 1);
            if (slot < 32) exid_s[wid][slot] = lane * 8 + j;
        }
    }
    __syncwarp();
    const int nc = min(ncs_s[wid], 32);

    // each lane c < nc: EXACT ascending-k single-accumulator fmaf chain
    if (lane < nc) {
        const int e = exid_s[wid][lane];
        const float4* h4 = (const float4*)(A + (size_t)warp * K);
        const float4* w4 = (const float4*)(W + (size_t)e * K);
        float acc = 0.0f;
#pragma unroll 8
        for (int it = 0; it < K / 4; it++) {
            const float4 hv = h4[it];
            const float4 wv = w4[it];
            acc = fmaf(hv.x, wv.x, acc);
            acc = fmaf(hv.y, wv.y, acc);
            acc = fmaf(hv.z, wv.z, acc);
            acc = fmaf(hv.w, wv.w, acc);
        }
        const float sp = fmaxf(acc, 0.0f) + log1pf(expf(-fabsf(acc)));
        exsc_s[wid][lane] = sqrtf(sp);
    }
    __syncwarp();

    // patch exact scores into owning lanes
    for (int c = 0; c < nc; c++) {
        const int e = exid_s[wid][c];
        if ((e >> 3) == lane) {
            const int j = e & 7;
            score[j] = exsc_s[wid][c];
            selsc[j] = score[j] + biasv[j];
        }
    }

    // final selection + weights + rewrite
#pragma unroll
    for (int j = 0; j < 8; j++) sel[j] = false;
    sumw = 0.0f;
#pragma unroll
    for (int it = 0; it < 8; it++) {
        float bestv = -INFINITY;
        int bestj = -1;
#pragma unroll
        for (int j = 0; j < 8; j++)
            if (selsc[j] > bestv) { bestv = selsc[j]; bestj = j; }
        int beste = (bestj >= 0) ? (lane * 8 + bestj) : 0x7fffffff;
        warp_argmax(bestv, beste);
        if ((beste >> 3) == lane) {
            const int j = beste & 7;
            sel[j] = true;
            selsc[j] = -INFINITY;
            sumw += score[j];
        }
    }
    tot = sumw;
#pragma unroll
    for (int off = 16; off > 0; off >>= 1)
        tot += __shfl_xor_sync(0xffffffffu, tot, off);
    scale = 2.5f / fmaxf(tot, 1e-12f);

    {
        float4 p0, p1, m0, m1;
        p0.x = sel[0] ? score[0]*scale : 0.0f;  m0.x = sel[0] ? 1.0f : 0.0f;
        p0.y = sel[1] ? score[1]*scale : 0.0f;  m0.y = sel[1] ? 1.0f : 0.0f;
        p0.z = sel[2] ? score[2]*scale : 0.0f;  m0.z = sel[2] ? 1.0f : 0.0f;
        p0.w = sel[3] ? score[3]*scale : 0.0f;  m0.w = sel[3] ? 1.0f : 0.0f;
        p1.x = sel[4] ? score[4]*scale : 0.0f;  m1.x = sel[4] ? 1.0f : 0.0f;
        p1.y = sel[5] ? score[5]*scale : 0.0f;  m1.y = sel[5] ? 1.0f : 0.0f;
        p1.z = sel[6] ? score[6]*scale : 0.0f;  m1.z = sel[6] ? 1.0f : 0.0f;
        p1.w = sel[7] ? score[7]*scale : 0.0f;  m1.w = sel[7] ? 1.0f : 0.0f;
        *(float4*)(probs + orow + lane * 8)     = p0;
        *(float4*)(probs + orow + lane * 8 + 4) = p1;
        *(float4*)(rmap  + orow + lane * 8)     = m0;
        *(float4*)(rmap  + orow + lane * 8 + 4) = m1;
    }
}

extern "C" void kernel_launch(void* const* d_in, const int* in_sizes, int n_in,
                              void* d_out, int out_size)
{
    const float* hidden = (const float*)d_in[0];
    const float* weight = (const float*)d_in[1];
    const float* bias   = (const float*)d_in[2];

    const int E = in_sizes[2];
    const int D = in_sizes[1] / E;
    const int N = in_sizes[0] / D;

    float* out   = (float*)d_out;
    float* probs = out;
    float* rmap  = out + (size_t)N * E;

    float* logits = nullptr;
    cudaGetSymbolAddress((void**)&logits, g_logits);

    cudaFuncSetAttribute(gemm_tf32_kernel,
                         cudaFuncAttributeMaxDynamicSharedMemorySize, SMEM_BYTES);

    dim3 grid(E / BN, N / BM);   // (2, 128)
    gemm_tf32_kernel<<<grid, 128, SMEM_BYTES>>>(hidden, weight, logits, E, D);

    router_fused_kernel<<<N / 8, 256>>>(logits, bias, hidden, weight,
                                        probs, rmap, N, D);

    (void)n_in; (void)out_size;
}

// round 17
// speedup vs baseline: 1.1576x; 1.1576x over previous
#include <cuda_runtime.h>
#include <math.h>
#include <stdint.h>

// ---------------------------------------------------------------------------
// DeepseekV4LearnedRouter — 1-pass TF32 mma.sync GEMM (validated 253us config)
// + vectorized top-8 + warp-per-token refinement with register-pipelined
//   SACRED CHAIN: ascending-k single-accumulator fmaf (matches reference fp32
//   rounding on boundary tokens; arithmetic order must not change).
// ---------------------------------------------------------------------------

#define BM 128
#define BN 128
#define KC 32
#define SA 36                         // smem row stride (f32); conflict-free frags
#define TILE_WORDS (128 * SA)         // 4608
#define STAGE_WORDS (2 * TILE_WORDS)  // 9216
#define SMEM_BYTES (2 * STAGE_WORDS * 4)   // 73728

#define MAX_N 16384
#define MAX_E 256
#define TAU 2e-3f

__device__ float g_logits[(size_t)MAX_N * MAX_E];
__device__ int   g_flag_count;
__device__ int   g_flag_list[MAX_N];

__device__ __forceinline__ uint32_t smem_u32(const void* p) {
    uint32_t a;
    asm("{ .reg .u64 t; cvta.to.shared.u64 t, %1; cvt.u32.u64 %0, t; }" : "=r"(a) : "l"(p));
    return a;
}
__device__ __forceinline__ uint32_t f2tf32(float x) {
    uint32_t r;
    asm("cvt.rna.tf32.f32 %0, %1;" : "=r"(r) : "f"(x));
    return r;
}
__device__ __forceinline__ void cp_async16(uint32_t saddr, const void* g) {
    asm volatile("cp.async.cg.shared.global [%0], [%1], 16;" :: "r"(saddr), "l"(g));
}
__device__ __forceinline__ void cp_commit() {
    asm volatile("cp.async.commit_group;" ::: "memory");
}
template <int N>
__device__ __forceinline__ void cp_wait() {
    asm volatile("cp.async.wait_group %0;" :: "n"(N) : "memory");
}
__device__ __forceinline__ void mma_tf32(float* d, const uint32_t* a, const uint32_t* b) {
    asm volatile(
        "mma.sync.aligned.m16n8k8.row.col.f32.tf32.tf32.f32 "
        "{%0,%1,%2,%3}, {%4,%5,%6,%7}, {%8,%9}, {%0,%1,%2,%3};"
        : "+f"(d[0]), "+f"(d[1]), "+f"(d[2]), "+f"(d[3])
        : "r"(a[0]), "r"(a[1]), "r"(a[2]), "r"(a[3]), "r"(b[0]), "r"(b[1]));
}
__device__ __forceinline__ void warp_argmax(float& bestv, int& beste) {
#pragma unroll
    for (int off = 16; off > 0; off >>= 1) {
        const float ov = __shfl_xor_sync(0xffffffffu, bestv, off);
        const int   oe = __shfl_xor_sync(0xffffffffu, beste, off);
        if (ov > bestv || (ov == bestv && oe < beste)) { bestv = ov; beste = oe; }
    }
}

// ---------------- GEMM: logits = A @ W^T (1-pass TF32, 64x64 warp tiles) ----
__global__ __launch_bounds__(128, 2)
void gemm_tf32_kernel(const float* __restrict__ A,
                      const float* __restrict__ W,
                      float* __restrict__ C,
                      int E, int K)
{
    extern __shared__ float sm[];
    const uint32_t sbase = smem_u32(sm);

    const int tid  = threadIdx.x;
    const int lane = tid & 31;
    const int w    = tid >> 5;         // 0..3
    const int wm   = w & 1;            // m offset 64*wm
    const int wn   = w >> 1;           // n offset 64*wn
    const int g    = lane >> 2;        // 0..7
    const int t    = lane & 3;         // 0..3

    const int nBase = blockIdx.x * BN;
    const int mBase = blockIdx.y * BM;
    const int KT    = K / KC;          // 128

    const float* Ag = A + (size_t)mBase * K;
    const float* Wg = W + (size_t)nBase * K;

    auto load_stage = [&](int stage, int k0) {
        const uint32_t sA = sbase + (uint32_t)stage * STAGE_WORDS * 4;
        const uint32_t sW = sA + TILE_WORDS * 4;
#pragma unroll
        for (int i = 0; i < 8; i++) {
            const int c   = tid + i * 128;
            const int row = c >> 3;
            const int c8  = c & 7;
            cp_async16(sA + (uint32_t)(row * SA + c8 * 4) * 4,
                       Ag + (size_t)row * K + k0 + c8 * 4);
        }
#pragma unroll
        for (int i = 0; i < 8; i++) {
            const int c   = tid + i * 128;
            const int row = c >> 3;
            const int c8  = c & 7;
            cp_async16(sW + (uint32_t)(row * SA + c8 * 4) * 4,
                       Wg + (size_t)row * K + k0 + c8 * 4);
        }
        cp_commit();
    };

    float acc[4][8][4];
#pragma unroll
    for (int mt = 0; mt < 4; mt++)
#pragma unroll
        for (int nt = 0; nt < 8; nt++)
#pragma unroll
            for (int i = 0; i < 4; i++)
                acc[mt][nt][i] = 0.0f;

    load_stage(0, 0);
    load_stage(1, KC);

    for (int kt = 0; kt < KT; ++kt) {
        cp_wait<1>();
        __syncthreads();

        const float* Asm = sm + (kt & 1) * STAGE_WORDS;
        const float* Wsm = Asm + TILE_WORDS;
        const float* ap = Asm + (wm * 64 + g) * SA;
        const float* bp = Wsm + (wn * 64 + g) * SA;

#pragma unroll
        for (int ks = 0; ks < KC / 8; ks++) {
            const int k0 = ks * 8 + t;

            uint32_t Bh[16];
#pragma unroll
            for (int nt = 0; nt < 8; nt++) {
                Bh[nt * 2]     = f2tf32(bp[nt * 8 * SA + k0]);
                Bh[nt * 2 + 1] = f2tf32(bp[nt * 8 * SA + k0 + 4]);
            }
            uint32_t Ah[16];
#pragma unroll
            for (int mt = 0; mt < 4; mt++) {
                Ah[mt * 4 + 0] = f2tf32(ap[mt * 16 * SA + k0]);
                Ah[mt * 4 + 1] = f2tf32(ap[mt * 16 * SA + 8 * SA + k0]);
                Ah[mt * 4 + 2] = f2tf32(ap[mt * 16 * SA + k0 + 4]);
                Ah[mt * 4 + 3] = f2tf32(ap[mt * 16 * SA + 8 * SA + k0 + 4]);
            }

#pragma unroll
            for (int mt = 0; mt < 4; mt++)
#pragma unroll
                for (int nt = 0; nt < 8; nt++)
                    mma_tf32(acc[mt][nt], &Ah[mt * 4], &Bh[nt * 2]);
        }

        __syncthreads();
        if (kt + 2 < KT) load_stage(kt & 1, (kt + 2) * KC);
        else cp_commit();
    }

#pragma unroll
    for (int mt = 0; mt < 4; mt++) {
        const int row0 = mBase + wm * 64 + mt * 16 + g;
#pragma unroll
        for (int nt = 0; nt < 8; nt++) {
            const int col = nBase + wn * 64 + nt * 8 + 2 * t;
            float2* p0 = (float2*)(C + (size_t)row0 * E + col);
            float2* p1 = (float2*)(C + (size_t)(row0 + 8) * E + col);
            *p0 = make_float2(acc[mt][nt][0], acc[mt][nt][1]);
            *p1 = make_float2(acc[mt][nt][2], acc[mt][nt][3]);
        }
    }
}

// ---------------- top-8 routing + flagging (vectorized, e = lane*8+j) -------
__global__ __launch_bounds__(256)
void router_topk_kernel(const float* __restrict__ logits,
                        const float* __restrict__ bias,
                        float* __restrict__ probs,
                        float* __restrict__ rmap,
                        int N)
{
    const int warp = (blockIdx.x * blockDim.x + threadIdx.x) >> 5;
    const int lane = threadIdx.x & 31;
    if (warp >= N) return;

    const float* lrow = logits + (size_t)warp * 256;

    float x[8], biasv[8];
    {
        const float4 l0 = *(const float4*)(lrow + lane * 8);
        const float4 l1 = *(const float4*)(lrow + lane * 8 + 4);
        x[0]=l0.x; x[1]=l0.y; x[2]=l0.z; x[3]=l0.w;
        x[4]=l1.x; x[5]=l1.y; x[6]=l1.z; x[7]=l1.w;
        const float4 b0 = *(const float4*)(bias + lane * 8);
        const float4 b1 = *(const float4*)(bias + lane * 8 + 4);
        biasv[0]=b0.x; biasv[1]=b0.y; biasv[2]=b0.z; biasv[3]=b0.w;
        biasv[4]=b1.x; biasv[5]=b1.y; biasv[6]=b1.z; biasv[7]=b1.w;
    }

    float score[8], selsc[8];
    bool  sel[8];
#pragma unroll
    for (int j = 0; j < 8; j++) {
        const float sp = fmaxf(x[j], 0.0f) + log1pf(expf(-fabsf(x[j])));
        score[j] = sqrtf(sp);
        selsc[j] = score[j] + biasv[j];
        sel[j] = false;
    }

    float sumw = 0.0f, v8 = 0.0f, v9 = 0.0f;
#pragma unroll
    for (int it = 0; it < 9; it++) {
        float bestv = -INFINITY;
        int bestj = -1;
#pragma unroll
        for (int j = 0; j < 8; j++)
            if (selsc[j] > bestv) { bestv = selsc[j]; bestj = j; }
        int beste = (bestj >= 0) ? (lane * 8 + bestj) : 0x7fffffff;
        warp_argmax(bestv, beste);
        if (it == 7) v8 = bestv;
        if (it == 8) { v9 = bestv; break; }
        if ((beste >> 3) == lane) {
            const int j = beste & 7;
            sel[j] = true;
            selsc[j] = -INFINITY;
            sumw += score[j];
        }
    }

    float tot = sumw;
#pragma unroll
    for (int off = 16; off > 0; off >>= 1)
        tot += __shfl_xor_sync(0xffffffffu, tot, off);
    const float scale = 2.5f / fmaxf(tot, 1e-12f);

    const size_t orow = (size_t)warp * 256;
    float4 p0, p1, m0, m1;
    p0.x = sel[0] ? score[0]*scale : 0.0f;  m0.x = sel[0] ? 1.0f : 0.0f;
    p0.y = sel[1] ? score[1]*scale : 0.0f;  m0.y = sel[1] ? 1.0f : 0.0f;
    p0.z = sel[2] ? score[2]*scale : 0.0f;  m0.z = sel[2] ? 1.0f : 0.0f;
    p0.w = sel[3] ? score[3]*scale : 0.0f;  m0.w = sel[3] ? 1.0f : 0.0f;
    p1.x = sel[4] ? score[4]*scale : 0.0f;  m1.x = sel[4] ? 1.0f : 0.0f;
    p1.y = sel[5] ? score[5]*scale : 0.0f;  m1.y = sel[5] ? 1.0f : 0.0f;
    p1.z = sel[6] ? score[6]*scale : 0.0f;  m1.z = sel[6] ? 1.0f : 0.0f;
    p1.w = sel[7] ? score[7]*scale : 0.0f;  m1.w = sel[7] ? 1.0f : 0.0f;
    *(float4*)(probs + orow + lane * 8)     = p0;
    *(float4*)(probs + orow + lane * 8 + 4) = p1;
    *(float4*)(rmap  + orow + lane * 8)     = m0;
    *(float4*)(rmap  + orow + lane * 8 + 4) = m1;

    if (lane == 0 && (v8 - v9) < TAU) {
        const int idx = atomicAdd(&g_flag_count, 1);
        g_flag_list[idx] = warp;
    }
}

// ---------------- warp-per-token refinement (pipelined sacred chain) --------
__global__ __launch_bounds__(128)
void refine_kernel(const float* __restrict__ A,
                   const float* __restrict__ W,
                   const float* __restrict__ bias,
                   const float* __restrict__ logits,
                   float* __restrict__ probs,
                   float* __restrict__ rmap,
                   int K)
{
    __shared__ float exsc_s[4][32];
    __shared__ int   exid_s[4][32];
    __shared__ int   ncs_s[4];

    const int wid  = threadIdx.x >> 5;
    const int lane = threadIdx.x & 31;
    const int cnt  = g_flag_count;
    const int gw   = blockIdx.x * 4 + wid;
    const int stride = gridDim.x * 4;

    for (int i = gw; i < cnt; i += stride) {
        const int tk = g_flag_list[i];
        const float* lrow = logits + (size_t)tk * 256;

        float score[8], selsc[8], biasv[8];
#pragma unroll
        for (int j = 0; j < 8; j++) {
            const int e = j * 32 + lane;
            const float x = lrow[e];
            const float sp = fmaxf(x, 0.0f) + log1pf(expf(-fabsf(x)));
            score[j] = sqrtf(sp);
            biasv[j] = bias[e];
            selsc[j] = score[j] + biasv[j];
        }

        // approx v8
        float tmp[8];
#pragma unroll
        for (int j = 0; j < 8; j++) tmp[j] = selsc[j];
        float v8 = -INFINITY;
#pragma unroll
        for (int it = 0; it < 8; it++) {
            float bestv = -INFINITY;
            int bestj = -1;
#pragma unroll
            for (int j = 0; j < 8; j++)
                if (tmp[j] > bestv) { bestv = tmp[j]; bestj = j; }
            int beste = (bestj >= 0) ? (bestj * 32 + lane) : 0x7fffffff;
            warp_argmax(bestv, beste);
            if (it == 7) v8 = bestv;
            if ((beste & 31) == lane) tmp[beste >> 5] = -INFINITY;
        }

        // gather boundary candidates
        if (lane == 0) ncs_s[wid] = 0;
        __syncwarp();
#pragma unroll
        for (int j = 0; j < 8; j++) {
            if (fabsf(selsc[j] - v8) <= TAU) {
                const int slot = atomicAdd(&ncs_s[wid], 1);
                if (slot < 32) exid_s[wid][slot] = j * 32 + lane;
            }
        }
        __syncwarp();
        const int nc = min(ncs_s[wid], 32);

        // SACRED CHAIN per candidate lane: ascending-k single-acc fmaf.
        // Loads manually double-buffered in batches of 8 float4 (order of
        // ARITHMETIC unchanged; only loads are hoisted).
        if (lane < nc) {
            const int e = exid_s[wid][lane];
            const float4* h4 = (const float4*)(A + (size_t)tk * K);
            const float4* w4 = (const float4*)(W + (size_t)e * K);
            const int NB = K / 32;          // batches of 8 float4 (=32 floats)

            float4 ha[8], wa[8], hb[8], wb[8];
            float acc = 0.0f;
#pragma unroll
            for (int j = 0; j < 8; j++) { ha[j] = h4[j]; wa[j] = w4[j]; }

            for (int b = 0; b < NB; b += 2) {
                // prefetch batch b+1 into B
#pragma unroll
                for (int j = 0; j < 8; j++) {
                    hb[j] = h4[(b + 1) * 8 + j];
                    wb[j] = w4[(b + 1) * 8 + j];
                }
                // chain batch b (buffer A)
#pragma unroll
                for (int j = 0; j < 8; j++) {
                    acc = fmaf(ha[j].x, wa[j].x, acc);
                    acc = fmaf(ha[j].y, wa[j].y, acc);
                    acc = fmaf(ha[j].z, wa[j].z, acc);
                    acc = fmaf(ha[j].w, wa[j].w, acc);
                }
                // prefetch batch b+2 into A
                if (b + 2 < NB) {
#pragma unroll
                    for (int j = 0; j < 8; j++) {
                        ha[j] = h4[(b + 2) * 8 + j];
                        wa[j] = w4[(b + 2) * 8 + j];
                    }
                }
                // chain batch b+1 (buffer B)
#pragma unroll
                for (int j = 0; j < 8; j++) {
                    acc = fmaf(hb[j].x, wb[j].x, acc);
                    acc = fmaf(hb[j].y, wb[j].y, acc);
                    acc = fmaf(hb[j].z, wb[j].z, acc);
                    acc = fmaf(hb[j].w, wb[j].w, acc);
                }
            }
            const float sp = fmaxf(acc, 0.0f) + log1pf(expf(-fabsf(acc)));
            exsc_s[wid][lane] = sqrtf(sp);
        }
        __syncwarp();

        // patch exact scores into owning lanes
        for (int c = 0; c < nc; c++) {
            const int e = exid_s[wid][c];
            if ((e & 31) == lane) {
                const int j = e >> 5;
                score[j] = exsc_s[wid][c];
                selsc[j] = score[j] + biasv[j];
            }
        }

        // final selection + weights + write
        bool sel[8];
#pragma unroll
        for (int j = 0; j < 8; j++) sel[j] = false;
        float sumw = 0.0f;
#pragma unroll
        for (int it = 0; it < 8; it++) {
            float bestv = -INFINITY;
            int bestj = -1;
#pragma unroll
            for (int j = 0; j < 8; j++)
                if (selsc[j] > bestv) { bestv = selsc[j]; bestj = j; }
            int beste = (bestj >= 0) ? (bestj * 32 + lane) : 0x7fffffff;
            warp_argmax(bestv, beste);
            if ((beste & 31) == lane) {
                const int j = beste >> 5;
                sel[j] = true;
                selsc[j] = -INFINITY;
                sumw += score[j];
            }
        }
        float tot = sumw;
#pragma unroll
        for (int off = 16; off > 0; off >>= 1)
            tot += __shfl_xor_sync(0xffffffffu, tot, off);
        const float scale = 2.5f / fmaxf(tot, 1e-12f);

#pragma unroll
        for (int j = 0; j < 8; j++) {
            const int e = j * 32 + lane;
            const size_t o = (size_t)tk * 256 + e;
            probs[o] = sel[j] ? score[j] * scale : 0.0f;
            rmap[o]  = sel[j] ? 1.0f : 0.0f;
        }
    }
}

extern "C" void kernel_launch(void* const* d_in, const int* in_sizes, int n_in,
                              void* d_out, int out_size)
{
    const float* hidden = (const float*)d_in[0];
    const float* weight = (const float*)d_in[1];
    const float* bias   = (const float*)d_in[2];

    const int E = in_sizes[2];
    const int D = in_sizes[1] / E;
    const int N = in_sizes[0] / D;

    float* out   = (float*)d_out;
    float* probs = out;
    float* rmap  = out + (size_t)N * E;

    float* logits = nullptr;
    cudaGetSymbolAddress((void**)&logits, g_logits);
    void* fc = nullptr;
    cudaGetSymbolAddress(&fc, g_flag_count);

    cudaMemsetAsync(fc, 0, sizeof(int));

    cudaFuncSetAttribute(gemm_tf32_kernel,
                         cudaFuncAttributeMaxDynamicSharedMemorySize, SMEM_BYTES);

    dim3 grid(E / BN, N / BM);   // (2, 128)
    gemm_tf32_kernel<<<grid, 128, SMEM_BYTES>>>(hidden, weight, logits, E, D);

    router_topk_kernel<<<N / 8, 256>>>(logits, bias, probs, rmap, N);

    refine_kernel<<<444, 128>>>(hidden, weight, bias, logits, probs, rmap, D);

    (void)n_in; (void)out_size;
}